// round 5
// baseline (speedup 1.0000x reference)
#include <cuda_runtime.h>
#include <cuda_bf16.h>
#include <cstdint>

// Problem constants
#define H 64
#define B 16
#define L 512
#define OUT 2
#define TOKS_PER_BLOCK 16
#define BLOCKS_PER_BATCH (2 * L / TOKS_PER_BLOCK)    // 64
#define GRID1 (B * BLOCKS_PER_BATCH)                 // 1024

// Accumulator scratch + completion counter.
// Zero at module load; the finishing block resets both after use, so every
// graph replay sees them zeroed.
__device__ float g_h[B * H];
__device__ unsigned int g_count;

// ---------------------------------------------------------------------------
// Fused kernel: gather + contraction + accumulation; LAST block to finish
// runs the tiny MLP inline. R5 fix vs R4: epilogue shared memory shrunk from
// 27KB -> 8KB (union with the gather reduce buffer, w1 staging replaced by a
// warp-cooperative coalesced-register scheme) so occupancy is back to
// 8 blocks/SM.
// ---------------------------------------------------------------------------
__global__ __launch_bounds__(256, 8)
void fused_kernel(const int* __restrict__ s1,
                  const int* __restrict__ s2,
                  const float4* __restrict__ embed,
                  const float* __restrict__ sos,
                  const float* __restrict__ w1,
                  const float* __restrict__ b1,
                  const float* __restrict__ w2,
                  const float* __restrict__ b2,
                  float* __restrict__ out)
{
    __shared__ union {
        float sh[8][H];                       // gather cross-warp reduce (2KB)
        struct {                              // epilogue (8KB)
            float hs[B * H];
            float x[B][H];
        } epi;
    } u;

    const int bl  = blockIdx.x;
    const int b   = bl / BLOCKS_PER_BATCH;
    const int j0  = (bl % BLOCKS_PER_BATCH) * TOKS_PER_BLOCK;  // within [0, 1024)
    const int tid = threadIdx.x;
    const int h4  = tid & 15;
    const int wg  = tid >> 4;

    // This block's 16 tokens are entirely in s1 or entirely in s2.
    const int* sp = (j0 < L) ? (s1 + b * L + j0) : (s2 + b * L + (j0 - L));

    int toks[TOKS_PER_BLOCK];
    #pragma unroll
    for (int k = 0; k < TOKS_PER_BLOCK; k++)
        toks[k] = __ldg(&sp[k]);

    const float sw0 = __ldg(&sos[wg]);
    const float sw1 = __ldg(&sos[wg + 16]);
    const float sw2 = __ldg(&sos[wg + 32]);
    const float sw3 = __ldg(&sos[wg + 48]);

    float4 acc = make_float4(0.f, 0.f, 0.f, 0.f);

    #pragma unroll 4
    for (int k = 0; k < TOKS_PER_BLOCK; k++) {
        const float4* M = embed + (size_t)toks[k] * (H * H / 4);

        float4 m0 = __ldg(&M[(wg      ) * 16 + h4]);
        float4 m1 = __ldg(&M[(wg + 16) * 16 + h4]);
        float4 m2 = __ldg(&M[(wg + 32) * 16 + h4]);
        float4 m3 = __ldg(&M[(wg + 48) * 16 + h4]);

        acc.x = fmaf(sw0, m0.x, acc.x); acc.y = fmaf(sw0, m0.y, acc.y);
        acc.z = fmaf(sw0, m0.z, acc.z); acc.w = fmaf(sw0, m0.w, acc.w);
        acc.x = fmaf(sw1, m1.x, acc.x); acc.y = fmaf(sw1, m1.y, acc.y);
        acc.z = fmaf(sw1, m1.z, acc.z); acc.w = fmaf(sw1, m1.w, acc.w);
        acc.x = fmaf(sw2, m2.x, acc.x); acc.y = fmaf(sw2, m2.y, acc.y);
        acc.z = fmaf(sw2, m2.z, acc.z); acc.w = fmaf(sw2, m2.w, acc.w);
        acc.x = fmaf(sw3, m3.x, acc.x); acc.y = fmaf(sw3, m3.y, acc.y);
        acc.z = fmaf(sw3, m3.z, acc.z); acc.w = fmaf(sw3, m3.w, acc.w);
    }

    // Warp reduce: lane l and l+16 hold the same columns for adjacent wg rows.
    acc.x += __shfl_down_sync(0xffffffffu, acc.x, 16);
    acc.y += __shfl_down_sync(0xffffffffu, acc.y, 16);
    acc.z += __shfl_down_sync(0xffffffffu, acc.z, 16);
    acc.w += __shfl_down_sync(0xffffffffu, acc.w, 16);

    const int warp = tid >> 5;
    const int lane = tid & 31;
    if (lane < 16) {
        u.sh[warp][lane * 4 + 0] = acc.x;
        u.sh[warp][lane * 4 + 1] = acc.y;
        u.sh[warp][lane * 4 + 2] = acc.z;
        u.sh[warp][lane * 4 + 3] = acc.w;
    }
    __syncthreads();
    if (tid < H) {
        float s = 0.f;
        #pragma unroll
        for (int w = 0; w < 8; w++) s += u.sh[w][tid];
        atomicAdd(&g_h[b * H + tid], s);
    }

    // ---- completion detection -------------------------------------------
    __threadfence();                       // make our g_h atomics visible
    __syncthreads();                       // also: all reads of u.sh done
    __shared__ unsigned int is_last;
    if (tid == 0)
        is_last = (atomicAdd(&g_count, 1u) == GRID1 - 1u) ? 1u : 0u;
    __syncthreads();
    if (!is_last) return;

    // ---- MLP epilogue (last block only, 256 threads = 8 warps) ----------
    // out = relu(h @ w1^T + b1) @ w2^T + b2
    #pragma unroll
    for (int idx = tid; idx < B * H; idx += 256) {
        u.epi.hs[idx] = __ldcg(&g_h[idx]);  // L2 read (producers wrote via L2 atomics)
        g_h[idx] = 0.0f;                    // reset for next graph replay
    }
    __syncthreads();

    // First layer, warp-cooperative: warp w owns rows j = w*8 .. w*8+7.
    // Each row of w1 (256B) loaded coalesced into 2 regs/lane; dot with
    // hs[b][*] via shuffle reduction (independent chains across b -> ILP).
    #pragma unroll
    for (int r = 0; r < 8; r++) {
        const int j = warp * 8 + r;
        const float w1a = __ldg(&w1[j * H + lane]);
        const float w1b = __ldg(&w1[j * H + 32 + lane]);
        const float bj  = __ldg(&b1[j]);
        #pragma unroll
        for (int bb = 0; bb < B; bb++) {
            float p = u.epi.hs[bb * H + lane] * w1a
                    + u.epi.hs[bb * H + 32 + lane] * w1b;
            p += __shfl_down_sync(0xffffffffu, p, 16);
            p += __shfl_down_sync(0xffffffffu, p, 8);
            p += __shfl_down_sync(0xffffffffu, p, 4);
            p += __shfl_down_sync(0xffffffffu, p, 2);
            p += __shfl_down_sync(0xffffffffu, p, 1);
            if (lane == 0) u.epi.x[bb][j] = fmaxf(p + bj, 0.f);
        }
    }
    __syncthreads();

    // Second layer: 32 outputs.
    if (tid < B * OUT) {
        const int bb = tid >> 1;
        const int o  = tid & 1;
        float a = __ldg(&b2[o]);
        #pragma unroll
        for (int k = 0; k < H; k++)
            a = fmaf(u.epi.x[bb][k], __ldg(&w2[o * H + k]), a);
        out[bb * OUT + o] = a;
    }

    if (tid == 0) g_count = 0u;            // reset counter for next replay
}

// ---------------------------------------------------------------------------
// Launch
// Inputs (metadata order): s1, s2, embed, sos, w1, b1, w2, b2
// ---------------------------------------------------------------------------
extern "C" void kernel_launch(void* const* d_in, const int* in_sizes, int n_in,
                              void* d_out, int out_size)
{
    const int*    s1    = (const int*)   d_in[0];
    const int*    s2    = (const int*)   d_in[1];
    const float4* embed = (const float4*)d_in[2];
    const float*  sos   = (const float*) d_in[3];
    const float*  w1    = (const float*) d_in[4];
    const float*  b1    = (const float*) d_in[5];
    const float*  w2    = (const float*) d_in[6];
    const float*  b2    = (const float*) d_in[7];
    float* out = (float*)d_out;

    fused_kernel<<<GRID1, 256>>>(s1, s2, embed, sos, w1, b1, w2, b2, out);
}

// round 6
// speedup vs baseline: 1.4015x; 1.4015x over previous
#include <cuda_runtime.h>
#include <cuda_bf16.h>
#include <cstdint>

// Problem constants
#define H 64
#define B 16
#define L 512
#define OUT 2
#define TOKS_PER_BLOCK 16
#define BLOCKS_PER_BATCH (2 * L / TOKS_PER_BLOCK)    // 64
#define GRID1 (B * BLOCKS_PER_BATCH)                 // 1024

// Accumulator scratch: h[b][h] = sum over 1024 tokens of sos @ M_tok.
// Zero-initialized at module load; mlp_kernel resets it to zero after reading,
// so every graph replay sees it zeroed.
__device__ float g_h[B * H];

// ---------------------------------------------------------------------------
// Kernel 1: token gather + sos contraction + per-batch accumulation
// (byte-identical to the R3 version that ran ~39us standalone)
// ---------------------------------------------------------------------------
__global__ __launch_bounds__(256, 8)
void gather_contract_kernel(const int* __restrict__ s1,
                            const int* __restrict__ s2,
                            const float4* __restrict__ embed,
                            const float* __restrict__ sos)
{
    const int bl  = blockIdx.x;
    const int b   = bl / BLOCKS_PER_BATCH;
    const int j0  = (bl % BLOCKS_PER_BATCH) * TOKS_PER_BLOCK;  // within [0, 1024)
    const int tid = threadIdx.x;
    const int h4  = tid & 15;
    const int wg  = tid >> 4;

    // This block's 16 tokens are entirely in s1 or entirely in s2.
    const int* sp = (j0 < L) ? (s1 + b * L + j0) : (s2 + b * L + (j0 - L));

    int toks[TOKS_PER_BLOCK];
    #pragma unroll
    for (int k = 0; k < TOKS_PER_BLOCK; k++)
        toks[k] = __ldg(&sp[k]);

    const float sw0 = __ldg(&sos[wg]);
    const float sw1 = __ldg(&sos[wg + 16]);
    const float sw2 = __ldg(&sos[wg + 32]);
    const float sw3 = __ldg(&sos[wg + 48]);

    float4 acc = make_float4(0.f, 0.f, 0.f, 0.f);

    #pragma unroll 4
    for (int k = 0; k < TOKS_PER_BLOCK; k++) {
        const float4* M = embed + (size_t)toks[k] * (H * H / 4);

        float4 m0 = __ldg(&M[(wg      ) * 16 + h4]);
        float4 m1 = __ldg(&M[(wg + 16) * 16 + h4]);
        float4 m2 = __ldg(&M[(wg + 32) * 16 + h4]);
        float4 m3 = __ldg(&M[(wg + 48) * 16 + h4]);

        acc.x = fmaf(sw0, m0.x, acc.x); acc.y = fmaf(sw0, m0.y, acc.y);
        acc.z = fmaf(sw0, m0.z, acc.z); acc.w = fmaf(sw0, m0.w, acc.w);
        acc.x = fmaf(sw1, m1.x, acc.x); acc.y = fmaf(sw1, m1.y, acc.y);
        acc.z = fmaf(sw1, m1.z, acc.z); acc.w = fmaf(sw1, m1.w, acc.w);
        acc.x = fmaf(sw2, m2.x, acc.x); acc.y = fmaf(sw2, m2.y, acc.y);
        acc.z = fmaf(sw2, m2.z, acc.z); acc.w = fmaf(sw2, m2.w, acc.w);
        acc.x = fmaf(sw3, m3.x, acc.x); acc.y = fmaf(sw3, m3.y, acc.y);
        acc.w = fmaf(sw3, m3.w, acc.w); acc.z = fmaf(sw3, m3.z, acc.z);
    }

    // Warp reduce: lane l and l+16 hold the same columns for adjacent wg rows.
    acc.x += __shfl_down_sync(0xffffffffu, acc.x, 16);
    acc.y += __shfl_down_sync(0xffffffffu, acc.y, 16);
    acc.z += __shfl_down_sync(0xffffffffu, acc.z, 16);
    acc.w += __shfl_down_sync(0xffffffffu, acc.w, 16);

    __shared__ float sh[8][H];
    const int warp = tid >> 5;
    const int lane = tid & 31;
    if (lane < 16) {
        sh[warp][lane * 4 + 0] = acc.x;
        sh[warp][lane * 4 + 1] = acc.y;
        sh[warp][lane * 4 + 2] = acc.z;
        sh[warp][lane * 4 + 3] = acc.w;
    }
    __syncthreads();
    if (tid < H) {
        float s = 0.f;
        #pragma unroll
        for (int w = 0; w < 8; w++) s += sh[w][tid];
        atomicAdd(&g_h[b * H + tid], s);
    }
}

// ---------------------------------------------------------------------------
// Kernel 2: tiny MLP classifier, launched with PDL (programmatic stream
// serialization). The w1 staging (16KB, DRAM-latency bound) runs CONCURRENTLY
// with the gather kernel; only the g_h read waits on gather completion via
// cudaGridDependencySynchronize().
// ---------------------------------------------------------------------------
__global__ __launch_bounds__(1024, 1)
void mlp_kernel(const float* __restrict__ w1,
                const float* __restrict__ b1,
                const float* __restrict__ w2,
                const float* __restrict__ b2,
                float* __restrict__ out)
{
    __shared__ float w1s[H][H + 1];   // padded: bank(j*65+k) = (j+k)%32
    __shared__ float hs[B * H];
    __shared__ float x[B][H];

    const int tid = threadIdx.x;      // 0..1023

    // ---- preamble: independent of the gather; overlaps with it under PDL --
    #pragma unroll
    for (int idx = tid; idx < H * H; idx += 1024)
        w1s[idx >> 6][idx & 63] = __ldg(&w1[idx]);
    const int b = tid >> 6;
    const int j = tid & 63;
    const float b1j = __ldg(&b1[j]);

    // ---- wait for gather kernel completion (g_h fully accumulated) --------
    cudaGridDependencySynchronize();

    hs[tid] = g_h[tid];
    g_h[tid] = 0.0f;                  // reset for next graph replay
    __syncthreads();

    float acc = b1j;
    #pragma unroll
    for (int k = 0; k < H; k++)
        acc = fmaf(hs[b * H + k], w1s[j][k], acc);
    x[b][j] = fmaxf(acc, 0.f);
    __syncthreads();

    if (tid < B * OUT) {
        const int bb = tid >> 1;
        const int o  = tid & 1;
        float a = __ldg(&b2[o]);
        #pragma unroll
        for (int k = 0; k < H; k++)
            a = fmaf(x[bb][k], __ldg(&w2[o * H + k]), a);
        out[bb * OUT + o] = a;
    }
}

// ---------------------------------------------------------------------------
// Launch
// Inputs (metadata order): s1, s2, embed, sos, w1, b1, w2, b2
// ---------------------------------------------------------------------------
extern "C" void kernel_launch(void* const* d_in, const int* in_sizes, int n_in,
                              void* d_out, int out_size)
{
    const int*    s1    = (const int*)   d_in[0];
    const int*    s2    = (const int*)   d_in[1];
    const float4* embed = (const float4*)d_in[2];
    const float*  sos   = (const float*) d_in[3];
    const float*  w1    = (const float*) d_in[4];
    const float*  b1    = (const float*) d_in[5];
    const float*  w2    = (const float*) d_in[6];
    const float*  b2    = (const float*) d_in[7];
    float* out = (float*)d_out;

    gather_contract_kernel<<<GRID1, 256>>>(s1, s2, embed, sos);

    // PDL launch: mlp may start while gather is still running; its
    // cudaGridDependencySynchronize() enforces the data dependency.
    cudaLaunchConfig_t cfg = {};
    cfg.gridDim  = dim3(1, 1, 1);
    cfg.blockDim = dim3(1024, 1, 1);
    cfg.dynamicSmemBytes = 0;
    cfg.stream = 0;
    cudaLaunchAttribute attr[1];
    attr[0].id = cudaLaunchAttributeProgrammaticStreamSerialization;
    attr[0].val.programmaticStreamSerializationAllowed = 1;
    cfg.attrs = attr;
    cfg.numAttrs = 1;
    cudaLaunchKernelEx(&cfg, mlp_kernel, w1, b1, w2, b2, out);
}